// round 1
// baseline (speedup 1.0000x reference)
#include <cuda_runtime.h>
#include <cuda_bf16.h>

#define Bq 2
#define Sq 2048
#define Eq 1024
#define Hq 16
#define Dq 64

// Scratch buffers (no cudaMalloc allowed)
__device__ float g_qkv[(size_t)Bq * Sq * 3 * Eq];   // [B*S, 3E]
__device__ float g_attn[(size_t)Bq * Sq * Eq];      // [B*S, E] (b,s,h,d) flattened

// ---------------------------------------------------------------------------
// Classic 128x128x8 register-blocked SGEMM, 256 threads, 8x8 per thread.
// C[M,N] = A[M,K] @ B[K,N], all row-major, dims divisible by tile sizes.
// ---------------------------------------------------------------------------
__global__ __launch_bounds__(256) void sgemm128(
    const float* __restrict__ A, const float* __restrict__ B,
    float* __restrict__ C, int M, int N, int K)
{
    __shared__ float As[8][128];
    __shared__ float Bs[8][128];

    const int tid = threadIdx.x;
    const int tx = tid & 15;       // 0..15 (col group)
    const int ty = tid >> 4;       // 0..15 (row group)
    const int brow = blockIdx.y * 128;
    const int bcol = blockIdx.x * 128;

    // A-tile load mapping: 128 rows x 8 cols, one float4 per thread
    const int arow = tid >> 1;           // 0..127
    const int acol = (tid & 1) * 4;      // 0 or 4
    // B-tile load mapping: 8 rows x 128 cols, one float4 per thread
    const int brB = tid >> 5;            // 0..7
    const int bcB = (tid & 31) * 4;      // 0..124

    float acc[8][8];
#pragma unroll
    for (int i = 0; i < 8; i++)
#pragma unroll
        for (int j = 0; j < 8; j++) acc[i][j] = 0.f;

    for (int k0 = 0; k0 < K; k0 += 8) {
        float4 av = *(const float4*)&A[(size_t)(brow + arow) * K + k0 + acol];
        As[acol + 0][arow] = av.x;
        As[acol + 1][arow] = av.y;
        As[acol + 2][arow] = av.z;
        As[acol + 3][arow] = av.w;
        *(float4*)&Bs[brB][bcB] =
            *(const float4*)&B[(size_t)(k0 + brB) * N + bcol + bcB];
        __syncthreads();

#pragma unroll
        for (int k = 0; k < 8; k++) {
            float a[8], b[8];
#pragma unroll
            for (int i = 0; i < 8; i++) a[i] = As[k][ty * 8 + i];
#pragma unroll
            for (int j = 0; j < 8; j++) b[j] = Bs[k][tx * 8 + j];
#pragma unroll
            for (int i = 0; i < 8; i++)
#pragma unroll
                for (int j = 0; j < 8; j++) acc[i][j] += a[i] * b[j];
        }
        __syncthreads();
    }

#pragma unroll
    for (int i = 0; i < 8; i++) {
        float* crow = &C[(size_t)(brow + ty * 8 + i) * N + bcol + tx * 8];
        *(float4*)(crow)     = make_float4(acc[i][0], acc[i][1], acc[i][2], acc[i][3]);
        *(float4*)(crow + 4) = make_float4(acc[i][4], acc[i][5], acc[i][6], acc[i][7]);
    }
}

// ---------------------------------------------------------------------------
// Flash attention with fused RoPE. One CTA = (b, h, 64-query block).
// 256 threads as 16x16; each thread owns a 4x4 micro-tile.
// smem: Qs[64][64], KP[64][65] (K tile, later reused for P), Vs[64][65].
// ---------------------------------------------------------------------------
#define FA_SMEM ((64 * 64 + 2 * 64 * 65) * sizeof(float))

__global__ __launch_bounds__(256) void flash_attn_kernel(
    const float* __restrict__ qkv,
    const float* __restrict__ fcos, const float* __restrict__ fsin,
    float* __restrict__ attn)
{
    extern __shared__ float sm[];
    float* Qs = sm;               // [64][64]
    float* KP = sm + 64 * 64;     // [64][65]
    float* Vs = KP + 64 * 65;     // [64][65]

    const int tid = threadIdx.x;
    const int tx = tid & 15;
    const int ty = tid >> 4;
    const int qb = blockIdx.x;            // query block 0..31
    const int b  = blockIdx.y >> 4;
    const int h  = blockIdx.y & 15;
    const int qbase = qb * 64;
    const float scale = 0.125f;           // 1/sqrt(64)
    const size_t rs3 = 3 * Eq;
    const size_t base = (size_t)b * Sq * rs3 + (size_t)h * Dq;

    // ---- load Q tile with RoPE, pre-scaled ----
    for (int t = tid; t < 64 * 32; t += 256) {
        int r = t >> 5, pr = t & 31;
        int sg = qbase + r;
        float2 xv = *(const float2*)&qkv[base + (size_t)sg * rs3 + 2 * pr];
        float c = fcos[sg * 32 + pr], sn = fsin[sg * 32 + pr];
        Qs[r * 64 + 2 * pr]     = (xv.x * c - xv.y * sn) * scale;
        Qs[r * 64 + 2 * pr + 1] = (xv.x * sn + xv.y * c) * scale;
    }

    float m[4], l[4], o[4][4];
#pragma unroll
    for (int i = 0; i < 4; i++) {
        m[i] = -1e30f; l[i] = 0.f;
#pragma unroll
        for (int j = 0; j < 4; j++) o[i][j] = 0.f;
    }

    for (int kt = 0; kt <= qb; ++kt) {
        const int kbase = kt * 64;

        // ---- load K tile with RoPE ----
        for (int t = tid; t < 64 * 32; t += 256) {
            int r = t >> 5, pr = t & 31;
            int sg = kbase + r;
            float2 xv = *(const float2*)&qkv[base + Eq + (size_t)sg * rs3 + 2 * pr];
            float c = fcos[sg * 32 + pr], sn = fsin[sg * 32 + pr];
            KP[r * 65 + 2 * pr]     = xv.x * c - xv.y * sn;
            KP[r * 65 + 2 * pr + 1] = xv.x * sn + xv.y * c;
        }
        // ---- load V tile ----
        for (int t = tid; t < 64 * 16; t += 256) {
            int r = t >> 4, c4 = (t & 15) * 4;
            float4 v = *(const float4*)&qkv[base + 2 * Eq + (size_t)(kbase + r) * rs3 + c4];
            Vs[r * 65 + c4]     = v.x;
            Vs[r * 65 + c4 + 1] = v.y;
            Vs[r * 65 + c4 + 2] = v.z;
            Vs[r * 65 + c4 + 3] = v.w;
        }
        __syncthreads();

        // ---- S = Q K^T (already scaled via Q) ----
        float sv[4][4];
#pragma unroll
        for (int i = 0; i < 4; i++)
#pragma unroll
            for (int j = 0; j < 4; j++) sv[i][j] = 0.f;

#pragma unroll 8
        for (int d = 0; d < 64; ++d) {
            float qv[4], kv[4];
#pragma unroll
            for (int i = 0; i < 4; i++) qv[i] = Qs[(ty * 4 + i) * 64 + d];
#pragma unroll
            for (int j = 0; j < 4; j++) kv[j] = KP[(tx * 4 + j) * 65 + d];
#pragma unroll
            for (int i = 0; i < 4; i++)
#pragma unroll
                for (int j = 0; j < 4; j++) sv[i][j] += qv[i] * kv[j];
        }

        // ---- causal mask on the diagonal tile ----
        if (kt == qb) {
#pragma unroll
            for (int i = 0; i < 4; i++)
#pragma unroll
                for (int j = 0; j < 4; j++)
                    if (kbase + tx * 4 + j > qbase + ty * 4 + i) sv[i][j] = -1e30f;
        }

        // ---- online softmax (row = 16 lanes sharing ty) ----
        float corr[4];
#pragma unroll
        for (int i = 0; i < 4; i++) {
            float mx = sv[i][0];
#pragma unroll
            for (int j = 1; j < 4; j++) mx = fmaxf(mx, sv[i][j]);
#pragma unroll
            for (int off = 8; off > 0; off >>= 1)
                mx = fmaxf(mx, __shfl_xor_sync(0xffffffffu, mx, off));
            float mn = fmaxf(m[i], mx);
            float rsum = 0.f;
#pragma unroll
            for (int j = 0; j < 4; j++) {
                sv[i][j] = __expf(sv[i][j] - mn);
                rsum += sv[i][j];
            }
#pragma unroll
            for (int off = 8; off > 0; off >>= 1)
                rsum += __shfl_xor_sync(0xffffffffu, rsum, off);
            corr[i] = __expf(m[i] - mn);
            l[i] = l[i] * corr[i] + rsum;
            m[i] = mn;
#pragma unroll
            for (int j = 0; j < 4; j++) o[i][j] *= corr[i];
        }

        __syncthreads();   // everyone done reading KP as K
        // ---- P -> smem (reuse K buffer) ----
#pragma unroll
        for (int i = 0; i < 4; i++)
#pragma unroll
            for (int j = 0; j < 4; j++)
                KP[(ty * 4 + i) * 65 + tx * 4 + j] = sv[i][j];
        __syncthreads();

        // ---- O += P @ V ----
#pragma unroll 8
        for (int c = 0; c < 64; ++c) {
            float pv[4], vv[4];
#pragma unroll
            for (int i = 0; i < 4; i++) pv[i] = KP[(ty * 4 + i) * 65 + c];
#pragma unroll
            for (int j = 0; j < 4; j++) vv[j] = Vs[c * 65 + tx * 4 + j];
#pragma unroll
            for (int i = 0; i < 4; i++)
#pragma unroll
                for (int j = 0; j < 4; j++) o[i][j] += pv[i] * vv[j];
        }
        __syncthreads();   // before next tile overwrites KP/Vs
    }

    // ---- epilogue: normalize and store (b, s, h, d) ----
#pragma unroll
    for (int i = 0; i < 4; i++) {
        float inv = 1.f / l[i];
        int sg = qbase + ty * 4 + i;
        float4 r = make_float4(o[i][0] * inv, o[i][1] * inv,
                               o[i][2] * inv, o[i][3] * inv);
        *(float4*)&attn[((size_t)b * Sq + sg) * Eq + h * Dq + tx * 4] = r;
    }
}

// ---------------------------------------------------------------------------
extern "C" void kernel_launch(void* const* d_in, const int* in_sizes, int n_in,
                              void* d_out, int out_size)
{
    const float* x     = (const float*)d_in[0];
    const float* w_qkv = (const float*)d_in[1];
    const float* w_out = (const float*)d_in[2];
    const float* fcos  = (const float*)d_in[3];
    const float* fsin  = (const float*)d_in[4];
    float* out = (float*)d_out;

    float *qkv, *attn;
    cudaGetSymbolAddress((void**)&qkv, g_qkv);
    cudaGetSymbolAddress((void**)&attn, g_attn);

    // 1) QKV projection: [4096,1024] @ [1024,3072]
    sgemm128<<<dim3(3 * Eq / 128, Bq * Sq / 128), 256>>>(x, w_qkv, qkv,
                                                          Bq * Sq, 3 * Eq, Eq);

    // 2) fused RoPE + causal flash attention
    cudaFuncSetAttribute(flash_attn_kernel,
                         cudaFuncAttributeMaxDynamicSharedMemorySize, FA_SMEM);
    flash_attn_kernel<<<dim3(Sq / 64, Bq * Hq), 256, FA_SMEM>>>(qkv, fcos, fsin, attn);

    // 3) output projection: [4096,1024] @ [1024,1024]
    sgemm128<<<dim3(Eq / 128, Bq * Sq / 128), 256>>>(attn, w_out, out,
                                                      Bq * Sq, Eq, Eq);
}

// round 2
// speedup vs baseline: 1.2530x; 1.2530x over previous
#include <cuda_runtime.h>
#include <cuda_bf16.h>
#include <mma.h>

using namespace nvcuda;

#define Bq 2
#define Sq 2048
#define Eq 1024
#define Hq 16
#define Dq 64

// Scratch buffers (no cudaMalloc allowed)
__device__ float g_qkv[(size_t)Bq * Sq * 3 * Eq];   // [B*S, 3E]
__device__ float g_attn[(size_t)Bq * Sq * Eq];      // [B*S, E] (b,s,h,d) flattened

// ---------------------------------------------------------------------------
// TF32 tensor-core GEMM: C[M,N] = A[M,K] @ B[K,N], row-major.
// 128x128 block tile, K-tile 32, 256 threads = 8 warps.
// Warp grid 4(M) x 2(N): each warp owns a 32x64 tile = 2x4 wmma 16x16x8 frags.
// ---------------------------------------------------------------------------
#define GT_M 128
#define GT_N 128
#define GT_K 32
#define A_LD (GT_K + 4)    // 36 (mult of 4, 16B rows alignment: 36*4=144=9*16)
#define B_LD (GT_N + 4)    // 132

__global__ __launch_bounds__(256) void gemm_tf32(
    const float* __restrict__ A, const float* __restrict__ B,
    float* __restrict__ C, int M, int N, int K)
{
    __shared__ float As[GT_M * A_LD];
    __shared__ float Bs[GT_K * B_LD];

    const int tid = threadIdx.x;
    const int warp = tid >> 5;
    const int wm = warp & 3;          // 0..3 -> 32-row slab
    const int wn = warp >> 2;         // 0..1 -> 64-col slab
    const int brow = blockIdx.y * GT_M;
    const int bcol = blockIdx.x * GT_N;

    wmma::fragment<wmma::accumulator, 16, 16, 8, float> c[2][4];
#pragma unroll
    for (int i = 0; i < 2; i++)
#pragma unroll
        for (int j = 0; j < 4; j++) wmma::fill_fragment(c[i][j], 0.f);

    // load mappings (float4)
    const int arow0 = tid >> 3;            // 0..31, step 32 over 4 passes
    const int acol  = (tid & 7) * 4;       // 0..28
    const int brow0 = tid >> 5;            // 0..7, step 8 over 4 passes
    const int bcolL = (tid & 31) * 4;      // 0..124

    for (int k0 = 0; k0 < K; k0 += GT_K) {
#pragma unroll
        for (int p = 0; p < 4; p++) {
            int r = arow0 + p * 32;
            float4 v = *(const float4*)&A[(size_t)(brow + r) * K + k0 + acol];
            *(float4*)&As[r * A_LD + acol] = v;
        }
#pragma unroll
        for (int p = 0; p < 4; p++) {
            int r = brow0 + p * 8;
            float4 v = *(const float4*)&B[(size_t)(k0 + r) * N + bcol + bcolL];
            *(float4*)&Bs[r * B_LD + bcolL] = v;
        }
        __syncthreads();

#pragma unroll
        for (int kk = 0; kk < GT_K; kk += 8) {
            wmma::fragment<wmma::matrix_a, 16, 16, 8, wmma::precision::tf32,
                           wmma::row_major> a[2];
            wmma::fragment<wmma::matrix_b, 16, 16, 8, wmma::precision::tf32,
                           wmma::row_major> bfr[4];
#pragma unroll
            for (int i = 0; i < 2; i++) {
                wmma::load_matrix_sync(a[i], &As[(wm * 32 + i * 16) * A_LD + kk], A_LD);
#pragma unroll
                for (int t = 0; t < a[i].num_elements; t++)
                    a[i].x[t] = wmma::__float_to_tf32(a[i].x[t]);
            }
#pragma unroll
            for (int j = 0; j < 4; j++) {
                wmma::load_matrix_sync(bfr[j], &Bs[kk * B_LD + wn * 64 + j * 16], B_LD);
#pragma unroll
                for (int t = 0; t < bfr[j].num_elements; t++)
                    bfr[j].x[t] = wmma::__float_to_tf32(bfr[j].x[t]);
            }
#pragma unroll
            for (int i = 0; i < 2; i++)
#pragma unroll
                for (int j = 0; j < 4; j++)
                    wmma::mma_sync(c[i][j], a[i], bfr[j], c[i][j]);
        }
        __syncthreads();
    }

#pragma unroll
    for (int i = 0; i < 2; i++)
#pragma unroll
        for (int j = 0; j < 4; j++)
            wmma::store_matrix_sync(
                &C[(size_t)(brow + wm * 32 + i * 16) * N + bcol + wn * 64 + j * 16],
                c[i][j], N, wmma::mem_row_major);
}

// ---------------------------------------------------------------------------
// Flash attention with fused RoPE. One CTA = (b, h, 64-query block).
// 256 threads as 16x16; each thread owns a 4x4 micro-tile.
// smem: Qs[64][64], KP[64][65] (K tile, later reused for P), Vs[64][65].
// ---------------------------------------------------------------------------
#define FA_SMEM ((64 * 64 + 2 * 64 * 65) * sizeof(float))

__global__ __launch_bounds__(256) void flash_attn_kernel(
    const float* __restrict__ qkv,
    const float* __restrict__ fcos, const float* __restrict__ fsin,
    float* __restrict__ attn)
{
    extern __shared__ float sm[];
    float* Qs = sm;               // [64][64]
    float* KP = sm + 64 * 64;     // [64][65]
    float* Vs = KP + 64 * 65;     // [64][65]

    const int tid = threadIdx.x;
    const int tx = tid & 15;
    const int ty = tid >> 4;
    const int qb = blockIdx.x;            // query block 0..31
    const int b  = blockIdx.y >> 4;
    const int h  = blockIdx.y & 15;
    const int qbase = qb * 64;
    const float scale = 0.125f;           // 1/sqrt(64)
    const size_t rs3 = 3 * Eq;
    const size_t base = (size_t)b * Sq * rs3 + (size_t)h * Dq;

    // ---- load Q tile with RoPE, pre-scaled ----
    for (int t = tid; t < 64 * 32; t += 256) {
        int r = t >> 5, pr = t & 31;
        int sg = qbase + r;
        float2 xv = *(const float2*)&qkv[base + (size_t)sg * rs3 + 2 * pr];
        float c = fcos[sg * 32 + pr], sn = fsin[sg * 32 + pr];
        Qs[r * 64 + 2 * pr]     = (xv.x * c - xv.y * sn) * scale;
        Qs[r * 64 + 2 * pr + 1] = (xv.x * sn + xv.y * c) * scale;
    }

    float m[4], l[4], o[4][4];
#pragma unroll
    for (int i = 0; i < 4; i++) {
        m[i] = -1e30f; l[i] = 0.f;
#pragma unroll
        for (int j = 0; j < 4; j++) o[i][j] = 0.f;
    }

    for (int kt = 0; kt <= qb; ++kt) {
        const int kbase = kt * 64;

        // ---- load K tile with RoPE ----
        for (int t = tid; t < 64 * 32; t += 256) {
            int r = t >> 5, pr = t & 31;
            int sg = kbase + r;
            float2 xv = *(const float2*)&qkv[base + Eq + (size_t)sg * rs3 + 2 * pr];
            float c = fcos[sg * 32 + pr], sn = fsin[sg * 32 + pr];
            KP[r * 65 + 2 * pr]     = xv.x * c - xv.y * sn;
            KP[r * 65 + 2 * pr + 1] = xv.x * sn + xv.y * c;
        }
        // ---- load V tile ----
        for (int t = tid; t < 64 * 16; t += 256) {
            int r = t >> 4, c4 = (t & 15) * 4;
            float4 v = *(const float4*)&qkv[base + 2 * Eq + (size_t)(kbase + r) * rs3 + c4];
            Vs[r * 65 + c4]     = v.x;
            Vs[r * 65 + c4 + 1] = v.y;
            Vs[r * 65 + c4 + 2] = v.z;
            Vs[r * 65 + c4 + 3] = v.w;
        }
        __syncthreads();

        // ---- S = Q K^T (already scaled via Q) ----
        float sv[4][4];
#pragma unroll
        for (int i = 0; i < 4; i++)
#pragma unroll
            for (int j = 0; j < 4; j++) sv[i][j] = 0.f;

#pragma unroll 8
        for (int d = 0; d < 64; ++d) {
            float qv[4], kv[4];
#pragma unroll
            for (int i = 0; i < 4; i++) qv[i] = Qs[(ty * 4 + i) * 64 + d];
#pragma unroll
            for (int j = 0; j < 4; j++) kv[j] = KP[(tx * 4 + j) * 65 + d];
#pragma unroll
            for (int i = 0; i < 4; i++)
#pragma unroll
                for (int j = 0; j < 4; j++) sv[i][j] += qv[i] * kv[j];
        }

        // ---- causal mask on the diagonal tile ----
        if (kt == qb) {
#pragma unroll
            for (int i = 0; i < 4; i++)
#pragma unroll
                for (int j = 0; j < 4; j++)
                    if (kbase + tx * 4 + j > qbase + ty * 4 + i) sv[i][j] = -1e30f;
        }

        // ---- online softmax (row = 16 lanes sharing ty) ----
        float corr[4];
#pragma unroll
        for (int i = 0; i < 4; i++) {
            float mx = sv[i][0];
#pragma unroll
            for (int j = 1; j < 4; j++) mx = fmaxf(mx, sv[i][j]);
#pragma unroll
            for (int off = 8; off > 0; off >>= 1)
                mx = fmaxf(mx, __shfl_xor_sync(0xffffffffu, mx, off));
            float mn = fmaxf(m[i], mx);
            float rsum = 0.f;
#pragma unroll
            for (int j = 0; j < 4; j++) {
                sv[i][j] = __expf(sv[i][j] - mn);
                rsum += sv[i][j];
            }
#pragma unroll
            for (int off = 8; off > 0; off >>= 1)
                rsum += __shfl_xor_sync(0xffffffffu, rsum, off);
            corr[i] = __expf(m[i] - mn);
            l[i] = l[i] * corr[i] + rsum;
            m[i] = mn;
#pragma unroll
            for (int j = 0; j < 4; j++) o[i][j] *= corr[i];
        }

        __syncthreads();   // everyone done reading KP as K
        // ---- P -> smem (reuse K buffer) ----
#pragma unroll
        for (int i = 0; i < 4; i++)
#pragma unroll
            for (int j = 0; j < 4; j++)
                KP[(ty * 4 + i) * 65 + tx * 4 + j] = sv[i][j];
        __syncthreads();

        // ---- O += P @ V ----
#pragma unroll 8
        for (int c = 0; c < 64; ++c) {
            float pv[4], vv[4];
#pragma unroll
            for (int i = 0; i < 4; i++) pv[i] = KP[(ty * 4 + i) * 65 + c];
#pragma unroll
            for (int j = 0; j < 4; j++) vv[j] = Vs[c * 65 + tx * 4 + j];
#pragma unroll
            for (int i = 0; i < 4; i++)
#pragma unroll
                for (int j = 0; j < 4; j++) o[i][j] += pv[i] * vv[j];
        }
        __syncthreads();   // before next tile overwrites KP/Vs
    }

    // ---- epilogue: normalize and store (b, s, h, d) ----
#pragma unroll
    for (int i = 0; i < 4; i++) {
        float inv = 1.f / l[i];
        int sg = qbase + ty * 4 + i;
        float4 r = make_float4(o[i][0] * inv, o[i][1] * inv,
                               o[i][2] * inv, o[i][3] * inv);
        *(float4*)&attn[((size_t)b * Sq + sg) * Eq + h * Dq + tx * 4] = r;
    }
}

// ---------------------------------------------------------------------------
extern "C" void kernel_launch(void* const* d_in, const int* in_sizes, int n_in,
                              void* d_out, int out_size)
{
    const float* x     = (const float*)d_in[0];
    const float* w_qkv = (const float*)d_in[1];
    const float* w_out = (const float*)d_in[2];
    const float* fcos  = (const float*)d_in[3];
    const float* fsin  = (const float*)d_in[4];
    float* out = (float*)d_out;

    float *qkv, *attn;
    cudaGetSymbolAddress((void**)&qkv, g_qkv);
    cudaGetSymbolAddress((void**)&attn, g_attn);

    // 1) QKV projection: [4096,1024] @ [1024,3072] (tf32 tensor cores)
    gemm_tf32<<<dim3(3 * Eq / GT_N, Bq * Sq / GT_M), 256>>>(x, w_qkv, qkv,
                                                            Bq * Sq, 3 * Eq, Eq);

    // 2) fused RoPE + causal flash attention
    cudaFuncSetAttribute(flash_attn_kernel,
                         cudaFuncAttributeMaxDynamicSharedMemorySize, FA_SMEM);
    flash_attn_kernel<<<dim3(Sq / 64, Bq * Hq), 256, FA_SMEM>>>(qkv, fcos, fsin, attn);

    // 3) output projection: [4096,1024] @ [1024,1024] (tf32 tensor cores)
    gemm_tf32<<<dim3(Eq / GT_N, Bq * Sq / GT_M), 256>>>(attn, w_out, out,
                                                         Bq * Sq, Eq, Eq);
}

// round 3
// speedup vs baseline: 1.4811x; 1.1820x over previous
#include <cuda_runtime.h>
#include <cuda_bf16.h>
#include <mma.h>

using namespace nvcuda;

#define Bq 2
#define Sq 2048
#define Eq 1024
#define Hq 16
#define Dq 64

// Scratch buffers (no cudaMalloc allowed)
__device__ float g_qkv[(size_t)Bq * Sq * 3 * Eq];   // [B*S, 3E]
__device__ float g_attn[(size_t)Bq * Sq * Eq];      // [B*S, E] (b,s,h,d) flattened

// ---------------------------------------------------------------------------
// TF32 tensor-core GEMM v2: C[M,N] = A[M,K] @ B[K,N], row-major.
// 128x128x32 tile, 256 threads (8 warps, 4x2 warp grid, 32x64 per warp).
// Register-staged gmem prefetch + double-buffered smem (1 sync / k-tile).
// tf32 rounding done once at smem fill.
// ---------------------------------------------------------------------------
#define GT_M 128
#define GT_N 128
#define GT_K 32
#define A_LD (GT_K + 4)    // 36
#define B_LD (GT_N + 4)    // 132
#define GA_SZ (GT_M * A_LD)         // 4608
#define GB_SZ (GT_K * B_LD)         // 4224
#define GEMM_SMEM (2 * (GA_SZ + GB_SZ) * sizeof(float))   // 70656 B

__global__ __launch_bounds__(256) void gemm_tf32(
    const float* __restrict__ A, const float* __restrict__ B,
    float* __restrict__ C, int M, int N, int K)
{
    extern __shared__ float gsm[];
    float* As = gsm;                       // [2][GA_SZ]
    float* Bs = gsm + 2 * GA_SZ;           // [2][GB_SZ]

    const int tid = threadIdx.x;
    const int warp = tid >> 5;
    const int wm = warp & 3;
    const int wn = warp >> 2;
    const int brow = blockIdx.y * GT_M;
    const int bcol = blockIdx.x * GT_N;

    const int arow0 = tid >> 3;            // 0..31 (+p*32)
    const int acol  = (tid & 7) * 4;
    const int brow0 = tid >> 5;            // 0..7 (+p*8)
    const int bcolL = (tid & 31) * 4;

    wmma::fragment<wmma::accumulator, 16, 16, 8, float> c[2][4];
#pragma unroll
    for (int i = 0; i < 2; i++)
#pragma unroll
        for (int j = 0; j < 4; j++) wmma::fill_fragment(c[i][j], 0.f);

    float4 pa[4], pb[4];

    auto ldg_tile = [&](int k0) {
#pragma unroll
        for (int p = 0; p < 4; p++)
            pa[p] = *(const float4*)&A[(size_t)(brow + arow0 + p * 32) * K + k0 + acol];
#pragma unroll
        for (int p = 0; p < 4; p++)
            pb[p] = *(const float4*)&B[(size_t)(k0 + brow0 + p * 8) * N + bcol + bcolL];
    };
    auto sts_tile = [&](float* Ad, float* Bd) {
#pragma unroll
        for (int p = 0; p < 4; p++) {
            float* d = &Ad[(arow0 + p * 32) * A_LD + acol];
            d[0] = wmma::__float_to_tf32(pa[p].x);
            d[1] = wmma::__float_to_tf32(pa[p].y);
            d[2] = wmma::__float_to_tf32(pa[p].z);
            d[3] = wmma::__float_to_tf32(pa[p].w);
        }
#pragma unroll
        for (int p = 0; p < 4; p++) {
            float* d = &Bd[(brow0 + p * 8) * B_LD + bcolL];
            d[0] = wmma::__float_to_tf32(pb[p].x);
            d[1] = wmma::__float_to_tf32(pb[p].y);
            d[2] = wmma::__float_to_tf32(pb[p].z);
            d[3] = wmma::__float_to_tf32(pb[p].w);
        }
    };

    const int T = K / GT_K;
    ldg_tile(0);
    sts_tile(As, Bs);
    __syncthreads();

    for (int t = 0; t < T; t++) {
        const int cur = t & 1;
        if (t + 1 < T) ldg_tile((t + 1) * GT_K);

        float* Ac = As + cur * GA_SZ;
        float* Bc = Bs + cur * GB_SZ;
#pragma unroll
        for (int kk = 0; kk < GT_K; kk += 8) {
            wmma::fragment<wmma::matrix_a, 16, 16, 8, wmma::precision::tf32,
                           wmma::row_major> a[2];
            wmma::fragment<wmma::matrix_b, 16, 16, 8, wmma::precision::tf32,
                           wmma::row_major> bf[4];
#pragma unroll
            for (int i = 0; i < 2; i++)
                wmma::load_matrix_sync(a[i], &Ac[(wm * 32 + i * 16) * A_LD + kk], A_LD);
#pragma unroll
            for (int j = 0; j < 4; j++)
                wmma::load_matrix_sync(bf[j], &Bc[kk * B_LD + wn * 64 + j * 16], B_LD);
#pragma unroll
            for (int i = 0; i < 2; i++)
#pragma unroll
                for (int j = 0; j < 4; j++)
                    wmma::mma_sync(c[i][j], a[i], bf[j], c[i][j]);
        }

        if (t + 1 < T) {
            sts_tile(As + (cur ^ 1) * GA_SZ, Bs + (cur ^ 1) * GB_SZ);
            __syncthreads();
        }
    }

#pragma unroll
    for (int i = 0; i < 2; i++)
#pragma unroll
        for (int j = 0; j < 4; j++)
            wmma::store_matrix_sync(
                &C[(size_t)(brow + wm * 32 + i * 16) * N + bcol + wn * 64 + j * 16],
                c[i][j], N, wmma::mem_row_major);
}

// ---------------------------------------------------------------------------
// Flash attention v2: tf32 wmma for QK^T and PV, fused RoPE.
// CTA = (b, h, 64-query block), 256 threads = 8 warps (4 row x 2 col).
// Softmax/O-update in smem with fixed thread->row mapping (4 threads/row),
// so running max/sum/corr stay in registers.
// ---------------------------------------------------------------------------
#define F_LD 72
#define F_SZ (64 * F_LD)                   // 4608 floats per buffer
#define FA_SMEM (6 * F_SZ * sizeof(float)) // Qs,Ks,Vs,Ss,Ts,Os = 110592 B

__global__ __launch_bounds__(256) void flash_attn_tc(
    const float* __restrict__ qkv,
    const float* __restrict__ fcos, const float* __restrict__ fsin,
    float* __restrict__ attn)
{
    extern __shared__ float sm[];
    float* Qs = sm;
    float* Ks = Qs + F_SZ;
    float* Vs = Ks + F_SZ;
    float* Ss = Vs + F_SZ;
    float* Ts = Ss + F_SZ;
    float* Os = Ts + F_SZ;

    const int tid = threadIdx.x;
    const int warp = tid >> 5;
    const int wr = warp & 3;          // 16-row slab of S / O
    const int wc = warp >> 2;         // 32-col slab
    const int qb = blockIdx.x;
    const int b  = blockIdx.y >> 4;
    const int h  = blockIdx.y & 15;
    const int qbase = qb * 64;
    const size_t rs3 = 3 * Eq;
    const size_t base = (size_t)b * Sq * rs3 + (size_t)h * Dq;

    // softmax ownership: thread -> row rr, 16-col quarter qd
    const int rr = tid >> 2;
    const int qd = tid & 3;

    // ---- load Q tile with RoPE, pre-scaled, tf32-rounded ----
    for (int t = tid; t < 64 * 32; t += 256) {
        int r = t >> 5, pr = t & 31;
        int sg = qbase + r;
        float2 xv = *(const float2*)&qkv[base + (size_t)sg * rs3 + 2 * pr];
        float c = fcos[sg * 32 + pr], sn = fsin[sg * 32 + pr];
        Qs[r * F_LD + 2 * pr]     = wmma::__float_to_tf32((xv.x * c - xv.y * sn) * 0.125f);
        Qs[r * F_LD + 2 * pr + 1] = wmma::__float_to_tf32((xv.x * sn + xv.y * c) * 0.125f);
    }
    for (int t = tid; t < F_SZ; t += 256) Os[t] = 0.f;

    float mrow = -1e30f, lrow = 0.f, corr = 1.f;

    for (int kt = 0; kt <= qb; ++kt) {
        const int kbase = kt * 64;

        // ---- fill K (RoPE) and V tiles, tf32-rounded ----
        for (int t = tid; t < 64 * 32; t += 256) {
            int r = t >> 5, pr = t & 31;
            int sg = kbase + r;
            float2 xv = *(const float2*)&qkv[base + Eq + (size_t)sg * rs3 + 2 * pr];
            float c = fcos[sg * 32 + pr], sn = fsin[sg * 32 + pr];
            Ks[r * F_LD + 2 * pr]     = wmma::__float_to_tf32(xv.x * c - xv.y * sn);
            Ks[r * F_LD + 2 * pr + 1] = wmma::__float_to_tf32(xv.x * sn + xv.y * c);
        }
        for (int t = tid; t < 64 * 16; t += 256) {
            int r = t >> 4, c4 = (t & 15) * 4;
            float4 v = *(const float4*)&qkv[base + 2 * Eq + (size_t)(kbase + r) * rs3 + c4];
            float* d = &Vs[r * F_LD + c4];
            d[0] = wmma::__float_to_tf32(v.x);
            d[1] = wmma::__float_to_tf32(v.y);
            d[2] = wmma::__float_to_tf32(v.z);
            d[3] = wmma::__float_to_tf32(v.w);
        }
        __syncthreads();

        // ---- S = Q @ K^T via wmma (K row-major == K^T col-major) ----
        {
            wmma::fragment<wmma::accumulator, 16, 16, 8, float> cs[2];
            wmma::fill_fragment(cs[0], 0.f);
            wmma::fill_fragment(cs[1], 0.f);
#pragma unroll
            for (int kk = 0; kk < 64; kk += 8) {
                wmma::fragment<wmma::matrix_a, 16, 16, 8, wmma::precision::tf32,
                               wmma::row_major> a;
                wmma::load_matrix_sync(a, &Qs[(wr * 16) * F_LD + kk], F_LD);
#pragma unroll
                for (int j = 0; j < 2; j++) {
                    wmma::fragment<wmma::matrix_b, 16, 16, 8, wmma::precision::tf32,
                                   wmma::col_major> bk;
                    wmma::load_matrix_sync(bk, &Ks[(wc * 32 + j * 16) * F_LD + kk], F_LD);
                    wmma::mma_sync(cs[j], a, bk, cs[j]);
                }
            }
#pragma unroll
            for (int j = 0; j < 2; j++)
                wmma::store_matrix_sync(&Ss[(wr * 16) * F_LD + wc * 32 + j * 16],
                                        cs[j], F_LD, wmma::mem_row_major);
        }
        __syncthreads();

        // ---- online softmax on this thread's 16 columns of row rr ----
        {
            float* srow = &Ss[rr * F_LD + qd * 16];
            float v[16];
#pragma unroll
            for (int c = 0; c < 16; c++) v[c] = srow[c];
            if (kt == qb) {
#pragma unroll
                for (int c = 0; c < 16; c++)
                    if (kbase + qd * 16 + c > qbase + rr) v[c] = -1e30f;
            }
            float mx = v[0];
#pragma unroll
            for (int c = 1; c < 16; c++) mx = fmaxf(mx, v[c]);
            mx = fmaxf(mx, __shfl_xor_sync(0xffffffffu, mx, 1));
            mx = fmaxf(mx, __shfl_xor_sync(0xffffffffu, mx, 2));
            float mn = fmaxf(mrow, mx);
            corr = __expf(mrow - mn);
            mrow = mn;
            float rsum = 0.f;
#pragma unroll
            for (int c = 0; c < 16; c++) {
                v[c] = __expf(v[c] - mn);
                rsum += v[c];
            }
            rsum += __shfl_xor_sync(0xffffffffu, rsum, 1);
            rsum += __shfl_xor_sync(0xffffffffu, rsum, 2);
            lrow = lrow * corr + rsum;
#pragma unroll
            for (int c = 0; c < 16; c++) srow[c] = wmma::__float_to_tf32(v[c]);
        }
        __syncthreads();

        // ---- T = P @ V via wmma ----
        {
            wmma::fragment<wmma::accumulator, 16, 16, 8, float> cd[2];
            wmma::fill_fragment(cd[0], 0.f);
            wmma::fill_fragment(cd[1], 0.f);
#pragma unroll
            for (int kk = 0; kk < 64; kk += 8) {
                wmma::fragment<wmma::matrix_a, 16, 16, 8, wmma::precision::tf32,
                               wmma::row_major> a;
                wmma::load_matrix_sync(a, &Ss[(wr * 16) * F_LD + kk], F_LD);
#pragma unroll
                for (int j = 0; j < 2; j++) {
                    wmma::fragment<wmma::matrix_b, 16, 16, 8, wmma::precision::tf32,
                                   wmma::row_major> bv;
                    wmma::load_matrix_sync(bv, &Vs[kk * F_LD + wc * 32 + j * 16], F_LD);
                    wmma::mma_sync(cd[j], a, bv, cd[j]);
                }
            }
#pragma unroll
            for (int j = 0; j < 2; j++)
                wmma::store_matrix_sync(&Ts[(wr * 16) * F_LD + wc * 32 + j * 16],
                                        cd[j], F_LD, wmma::mem_row_major);
        }
        __syncthreads();

        // ---- O = O * corr + T (same thread->row mapping; corr in register) ----
        {
            float* orow = &Os[rr * F_LD + qd * 16];
            float* trow = &Ts[rr * F_LD + qd * 16];
#pragma unroll
            for (int c = 0; c < 16; c++) orow[c] = orow[c] * corr + trow[c];
        }
        // no trailing sync: next-iter fills touch only Ks/Vs and are ordered
        // by the sync after fill; each thread reads only its own O/T rows.
    }

    // ---- epilogue: this thread owns its O cells; normalize and store ----
    {
        float inv = 1.f / lrow;
        float* orow = &Os[rr * F_LD + qd * 16];
        float* op = &attn[((size_t)b * Sq + qbase + rr) * Eq + h * Dq + qd * 16];
#pragma unroll
        for (int c = 0; c < 16; c += 4) {
            float4 r = make_float4(orow[c] * inv, orow[c + 1] * inv,
                                   orow[c + 2] * inv, orow[c + 3] * inv);
            *(float4*)&op[c] = r;
        }
    }
}

// ---------------------------------------------------------------------------
extern "C" void kernel_launch(void* const* d_in, const int* in_sizes, int n_in,
                              void* d_out, int out_size)
{
    const float* x     = (const float*)d_in[0];
    const float* w_qkv = (const float*)d_in[1];
    const float* w_out = (const float*)d_in[2];
    const float* fcos  = (const float*)d_in[3];
    const float* fsin  = (const float*)d_in[4];
    float* out = (float*)d_out;

    float *qkv, *attn;
    cudaGetSymbolAddress((void**)&qkv, g_qkv);
    cudaGetSymbolAddress((void**)&attn, g_attn);

    cudaFuncSetAttribute(gemm_tf32,
                         cudaFuncAttributeMaxDynamicSharedMemorySize, GEMM_SMEM);
    cudaFuncSetAttribute(flash_attn_tc,
                         cudaFuncAttributeMaxDynamicSharedMemorySize, FA_SMEM);

    // 1) QKV projection: [4096,1024] @ [1024,3072]
    gemm_tf32<<<dim3(3 * Eq / GT_N, Bq * Sq / GT_M), 256, GEMM_SMEM>>>(
        x, w_qkv, qkv, Bq * Sq, 3 * Eq, Eq);

    // 2) fused RoPE + causal flash attention (tensor cores)
    flash_attn_tc<<<dim3(Sq / 64, Bq * Hq), 256, FA_SMEM>>>(qkv, fcos, fsin, attn);

    // 3) output projection: [4096,1024] @ [1024,1024]
    gemm_tf32<<<dim3(Eq / GT_N, Bq * Sq / GT_M), 256, GEMM_SMEM>>>(
        attn, w_out, out, Bq * Sq, Eq, Eq);
}